// round 1
// baseline (speedup 1.0000x reference)
#include <cuda_runtime.h>
#include <math.h>

#define BB 8
#define CC 96
#define NN 3136
#define KK 9

// ---------------- scratch (device globals: no allocations allowed) ----------
__device__ float g_y1[BB*CC*NN];
__device__ float g_xn[BB*CC*NN];
__device__ int   g_idx[BB*NN*KK];
__device__ float g_cat[BB*2*CC*NN];
__device__ float g_y2[BB*2*CC*NN];
__device__ float g_t [BB*4*CC*NN];
__device__ float g_s1[BB*CC*NN];
__device__ float g_s2[BB*CC*NN];

// ---------------- generic 1x1-conv GEMM: out[b,o,n] = sum_c W[o,c] in[b,c,n] + bias[o]
#define TN 128
#define TO 32
#define TKC 32
__global__ void gemm_bias_kernel(const float* __restrict__ in, const float* __restrict__ W,
                                 const float* __restrict__ bias, float* __restrict__ out,
                                 int Cin, int Cout)
{
    int b  = blockIdx.z;
    int o0 = blockIdx.y * TO;
    int n0 = blockIdx.x * TN;
    const float* inb = in + (size_t)b * Cin * NN;
    float* outb      = out + (size_t)b * Cout * NN;

    __shared__ float Ws[TKC][TO + 1];
    __shared__ float Is[TKC][TN];

    int tid = threadIdx.x;
    int tx = tid & 31;   // 4 cols each
    int ty = tid >> 5;   // 4 rows each

    float acc[4][4];
    #pragma unroll
    for (int i = 0; i < 4; i++)
        #pragma unroll
        for (int j = 0; j < 4; j++) acc[i][j] = 0.f;

    for (int k0 = 0; k0 < Cin; k0 += TKC) {
        // W tile (TO x TKC), stored transposed
        for (int i = tid; i < TO * TKC; i += 256) {
            int o = i >> 5, k = i & 31;
            Ws[k][o] = W[(size_t)(o0 + o) * Cin + k0 + k];
        }
        // In tile (TKC x TN)
        for (int i = tid; i < TKC * TN; i += 256) {
            int k = i >> 7, n = i & 127;
            int gn = n0 + n;
            Is[k][n] = (gn < NN) ? inb[(size_t)(k0 + k) * NN + gn] : 0.f;
        }
        __syncthreads();
        #pragma unroll 8
        for (int k = 0; k < TKC; k++) {
            float a0 = Ws[k][ty*4+0], a1 = Ws[k][ty*4+1];
            float a2 = Ws[k][ty*4+2], a3 = Ws[k][ty*4+3];
            float4 bv = *(const float4*)&Is[k][tx*4];
            acc[0][0] += a0*bv.x; acc[0][1] += a0*bv.y; acc[0][2] += a0*bv.z; acc[0][3] += a0*bv.w;
            acc[1][0] += a1*bv.x; acc[1][1] += a1*bv.y; acc[1][2] += a1*bv.z; acc[1][3] += a1*bv.w;
            acc[2][0] += a2*bv.x; acc[2][1] += a2*bv.y; acc[2][2] += a2*bv.z; acc[2][3] += a2*bv.w;
            acc[3][0] += a3*bv.x; acc[3][1] += a3*bv.y; acc[3][2] += a3*bv.z; acc[3][3] += a3*bv.w;
        }
        __syncthreads();
    }
    #pragma unroll
    for (int i = 0; i < 4; i++) {
        int o = o0 + ty*4 + i;
        float bb = bias[o];
        #pragma unroll
        for (int j = 0; j < 4; j++) {
            int n = n0 + tx*4 + j;
            if (n < NN) outb[(size_t)o * NN + n] = acc[i][j] + bb;
        }
    }
}

// ---------------- instance norm over N per (b,c) row, with fused epilogues
// EPI: 0=none, 1=gelu(exact), 2=relu, 3=add residual
template<int EPI>
__global__ void inorm_kernel(const float* in, float* out, const float* res)
{
    int row = blockIdx.x;                  // b*Ctot + c
    const float* x = in + (size_t)row * NN;
    float* y       = out + (size_t)row * NN;
    const float* r = res ? res + (size_t)row * NN : nullptr;

    float s = 0.f, ss = 0.f;
    for (int i = threadIdx.x; i < NN; i += blockDim.x) {
        float v = x[i]; s += v; ss += v * v;
    }
    __shared__ float red[2][32];
    #pragma unroll
    for (int o = 16; o; o >>= 1) {
        s  += __shfl_down_sync(0xffffffffu, s,  o);
        ss += __shfl_down_sync(0xffffffffu, ss, o);
    }
    int wid = threadIdx.x >> 5, lid = threadIdx.x & 31;
    if (!lid) { red[0][wid] = s; red[1][wid] = ss; }
    __syncthreads();
    if (wid == 0) {
        s  = (lid < (int)(blockDim.x >> 5)) ? red[0][lid] : 0.f;
        ss = (lid < (int)(blockDim.x >> 5)) ? red[1][lid] : 0.f;
        #pragma unroll
        for (int o = 16; o; o >>= 1) {
            s  += __shfl_down_sync(0xffffffffu, s,  o);
            ss += __shfl_down_sync(0xffffffffu, ss, o);
        }
        if (!lid) { red[0][0] = s; red[1][0] = ss; }
    }
    __syncthreads();
    float mean = red[0][0] * (1.f / NN);
    float var  = red[1][0] * (1.f / NN) - mean * mean;
    float rstd = rsqrtf(var + 1e-5f);
    for (int i = threadIdx.x; i < NN; i += blockDim.x) {
        float v = (x[i] - mean) * rstd;
        if (EPI == 1)      v = 0.5f * v * (1.f + erff(v * 0.70710678118654752f));
        else if (EPI == 2) v = fmaxf(v, 0.f);
        else if (EPI == 3) v += r[i];
        y[i] = v;
    }
}

// ---------------- per-pixel L2 normalization over channels (for kNN features)
__global__ void colnorm_kernel(const float* __restrict__ y1, float* __restrict__ xn)
{
    int b = blockIdx.y;
    int n = blockIdx.x * blockDim.x + threadIdx.x;
    if (n >= NN) return;
    const float* p = y1 + (size_t)b * CC * NN + n;
    float v[CC];
    float s = 0.f;
    #pragma unroll
    for (int c = 0; c < CC; c++) { v[c] = p[(size_t)c * NN]; s += v[c] * v[c]; }
    float rn = 1.f / fmaxf(sqrtf(s), 1e-12f);
    float* q = xn + (size_t)b * CC * NN + n;
    #pragma unroll
    for (int c = 0; c < CC; c++) q[(size_t)c * NN] = v[c] * rn;
}

// ---------------- fused distance GEMM + top-K=9 selection
// score(n,m) = rp[n,m] - 2*dot(xn_n, xn_m)  (sq terms == 1, drop: ordering identical)
#define KTR 64
#define KTC 128
#define SS_STRIDE 129
#define SMEM_KNN ((CC*KTR + CC*KTC + KTR*SS_STRIDE) * 4)

__global__ void knn_kernel(const float* __restrict__ xn, const float* __restrict__ rp,
                           int* __restrict__ idx)
{
    extern __shared__ float sm[];
    float* As = sm;                    // [CC][KTR]
    float* Bs = As + CC * KTR;         // [CC][KTC]
    float* Ss = Bs + CC * KTC;         // [KTR][SS_STRIDE]

    int b  = blockIdx.y;
    int r0 = blockIdx.x * KTR;         // NN = 64*49 exact
    const float* xb = xn + (size_t)b * CC * NN;
    int tid = threadIdx.x;

    for (int i = tid; i < CC * KTR; i += 256) {
        int c = i >> 6, r = i & 63;
        As[c * KTR + r] = xb[(size_t)c * NN + r0 + r];
    }

    float best[KK]; int bidx[KK];
    #pragma unroll
    for (int k = 0; k < KK; k++) { best[k] = 3.4e38f; bidx[k] = 0; }

    int rg = tid >> 4;     // 16 row groups * 4 rows
    int cg = tid & 15;     // 16 col groups * (4 + 4) cols (split halves: bank-friendly)

    for (int m0 = 0; m0 < NN; m0 += KTC) {
        __syncthreads();   // selectors done with Ss, As ready on first iter
        for (int i = tid; i < CC * KTC; i += 256) {
            int c = i >> 7, m = i & 127;
            int gm = m0 + m;
            Bs[c * KTC + m] = (gm < NN) ? xb[(size_t)c * NN + gm] : 0.f;
        }
        __syncthreads();

        float acc[4][8];
        #pragma unroll
        for (int i = 0; i < 4; i++)
            #pragma unroll
            for (int j = 0; j < 8; j++) acc[i][j] = 0.f;

        #pragma unroll 4
        for (int c = 0; c < CC; c++) {
            float a0 = As[c*KTR + rg*4 + 0];
            float a1 = As[c*KTR + rg*4 + 1];
            float a2 = As[c*KTR + rg*4 + 2];
            float a3 = As[c*KTR + rg*4 + 3];
            float4 b0 = *(const float4*)&Bs[c*KTC + cg*4];
            float4 b1 = *(const float4*)&Bs[c*KTC + 64 + cg*4];
            acc[0][0] += a0*b0.x; acc[0][1] += a0*b0.y; acc[0][2] += a0*b0.z; acc[0][3] += a0*b0.w;
            acc[0][4] += a0*b1.x; acc[0][5] += a0*b1.y; acc[0][6] += a0*b1.z; acc[0][7] += a0*b1.w;
            acc[1][0] += a1*b0.x; acc[1][1] += a1*b0.y; acc[1][2] += a1*b0.z; acc[1][3] += a1*b0.w;
            acc[1][4] += a1*b1.x; acc[1][5] += a1*b1.y; acc[1][6] += a1*b1.z; acc[1][7] += a1*b1.w;
            acc[2][0] += a2*b0.x; acc[2][1] += a2*b0.y; acc[2][2] += a2*b0.z; acc[2][3] += a2*b0.w;
            acc[2][4] += a2*b1.x; acc[2][5] += a2*b1.y; acc[2][6] += a2*b1.z; acc[2][7] += a2*b1.w;
            acc[3][0] += a3*b0.x; acc[3][1] += a3*b0.y; acc[3][2] += a3*b0.z; acc[3][3] += a3*b0.w;
            acc[3][4] += a3*b1.x; acc[3][5] += a3*b1.y; acc[3][6] += a3*b1.z; acc[3][7] += a3*b1.w;
        }

        #pragma unroll
        for (int i = 0; i < 4; i++) {
            int r = rg*4 + i;
            const float* rpr = rp + (size_t)(r0 + r) * NN;
            #pragma unroll
            for (int j = 0; j < 8; j++) {
                int m  = (j < 4) ? (cg*4 + j) : (64 + cg*4 + (j - 4));
                int gm = m0 + m;
                float rv = (gm < NN) ? __ldg(&rpr[gm]) : 0.f;
                Ss[r * SS_STRIDE + m] = rv - 2.f * acc[i][j];
            }
        }
        __syncthreads();

        if (tid < KTR) {
            int r = tid;
            int lim = (NN - m0 < KTC) ? (NN - m0) : KTC;
            for (int m = 0; m < lim; m++) {
                float s = Ss[r * SS_STRIDE + m];
                if (s < best[KK-1]) {
                    best[KK-1] = s; bidx[KK-1] = m0 + m;
                    #pragma unroll
                    for (int k = KK-1; k > 0; k--) {
                        if (best[k] < best[k-1]) {
                            float tv = best[k]; best[k] = best[k-1]; best[k-1] = tv;
                            int   ti = bidx[k]; bidx[k] = bidx[k-1]; bidx[k-1] = ti;
                        }
                    }
                }
            }
        }
    }

    if (tid < KTR) {
        int gr = r0 + tid;
        int* op = idx + ((size_t)b * NN + gr) * KK;
        #pragma unroll
        for (int k = 0; k < KK; k++) op[k] = bidx[k];
    }
}

// ---------------- max-relative gather + interleaved concat
// cat[b,2c,n] = xf ; cat[b,2c+1,n] = max_k( xf[idx[k]] - xf[n] )
__global__ void gather_kernel(const float* __restrict__ y1, const int* __restrict__ idx,
                              float* __restrict__ cat)
{
    int b = blockIdx.z;
    int c = blockIdx.y;
    int n = blockIdx.x * blockDim.x + threadIdx.x;
    if (n >= NN) return;
    const float* yb = y1 + ((size_t)b * CC + c) * NN;
    float own = yb[n];
    const int* ib = idx + ((size_t)b * NN + n) * KK;
    float m = -3.4e38f;
    #pragma unroll
    for (int k = 0; k < KK; k++) {
        float v = __ldg(&yb[ib[k]]);
        m = fmaxf(m, v - own);
    }
    float* cb = cat + (size_t)b * 2 * CC * NN;
    cb[(size_t)(2*c)     * NN + n] = own;
    cb[(size_t)(2*c + 1) * NN + n] = m;
}

// ---------------- host orchestration -----------------------------------------
static void run_grapher(const float* X, const float* rp,
                        const float* fc1w, const float* fc1b,
                        const float* mrw,  const float* mrb,
                        const float* fc2w, const float* fc2b,
                        float* out,
                        float* y1, float* xn, int* idx, float* cat, float* y2, float* t)
{
    dim3 gA((NN + TN - 1) / TN, CC / TO, BB);
    gemm_bias_kernel<<<gA, 256>>>(X, fc1w, fc1b, y1, CC, CC);
    inorm_kernel<0><<<BB * CC, 256>>>(y1, y1, nullptr);
    colnorm_kernel<<<dim3((NN + 255) / 256, BB), 256>>>(y1, xn);
    knn_kernel<<<dim3(NN / KTR, BB), 256, SMEM_KNN>>>(xn, rp, idx);
    gather_kernel<<<dim3((NN + 255) / 256, CC, BB), 256>>>(y1, idx, cat);
    dim3 gB((NN + TN - 1) / TN, 2 * CC / TO, BB);
    gemm_bias_kernel<<<gB, 256>>>(cat, mrw, mrb, y2, 2 * CC, 2 * CC);
    inorm_kernel<1><<<BB * 2 * CC, 256>>>(y2, y2, nullptr);
    dim3 gC((NN + TN - 1) / TN, CC / TO, BB);
    gemm_bias_kernel<<<gC, 256>>>(y2, fc2w, fc2b, t, 2 * CC, CC);
    inorm_kernel<3><<<BB * CC, 256>>>(t, out, X);
}

static void run_ffn(const float* X,
                    const float* w1, const float* b1,
                    const float* w2, const float* b2,
                    float* out, float* t, float* y1)
{
    dim3 gA((NN + TN - 1) / TN, 4 * CC / TO, BB);
    gemm_bias_kernel<<<gA, 256>>>(X, w1, b1, t, CC, 4 * CC);
    inorm_kernel<1><<<BB * 4 * CC, 256>>>(t, t, nullptr);
    dim3 gB((NN + TN - 1) / TN, CC / TO, BB);
    gemm_bias_kernel<<<gB, 256>>>(t, w2, b2, y1, 4 * CC, CC);
    inorm_kernel<3><<<BB * CC, 256>>>(y1, out, X);
}

extern "C" void kernel_launch(void* const* d_in, const int* in_sizes, int n_in,
                              void* d_out, int out_size)
{
    const float* X0 = (const float*)d_in[0];
    const float* rp = (const float*)d_in[1];

    float *y1, *xn, *cat, *y2, *t, *s1, *s2; int* idx;
    cudaGetSymbolAddress((void**)&y1,  g_y1);
    cudaGetSymbolAddress((void**)&xn,  g_xn);
    cudaGetSymbolAddress((void**)&idx, g_idx);
    cudaGetSymbolAddress((void**)&cat, g_cat);
    cudaGetSymbolAddress((void**)&y2,  g_y2);
    cudaGetSymbolAddress((void**)&t,   g_t);
    cudaGetSymbolAddress((void**)&s1,  g_s1);
    cudaGetSymbolAddress((void**)&s2,  g_s2);

    cudaFuncSetAttribute(knn_kernel, cudaFuncAttributeMaxDynamicSharedMemorySize, SMEM_KNN);

    // grapher 1: X0 -> s1
    run_grapher(X0, rp,
                (const float*)d_in[2], (const float*)d_in[3],
                (const float*)d_in[4], (const float*)d_in[5],
                (const float*)d_in[6], (const float*)d_in[7],
                s1, y1, xn, idx, cat, y2, t);
    // ffn 1: s1 -> s2
    run_ffn(s1,
            (const float*)d_in[14], (const float*)d_in[15],
            (const float*)d_in[16], (const float*)d_in[17],
            s2, t, y1);
    // mid: relu(inorm(s2)) -> s1
    inorm_kernel<2><<<BB * CC, 256>>>(s2, s1, nullptr);
    // grapher 2: s1 -> s2
    run_grapher(s1, rp,
                (const float*)d_in[8],  (const float*)d_in[9],
                (const float*)d_in[10], (const float*)d_in[11],
                (const float*)d_in[12], (const float*)d_in[13],
                s2, y1, xn, idx, cat, y2, t);
    // ffn 2: s2 -> s1
    run_ffn(s2,
            (const float*)d_in[18], (const float*)d_in[19],
            (const float*)d_in[20], (const float*)d_in[21],
            s1, t, y1);
    // final: out = X0 + inorm(s1)
    inorm_kernel<3><<<BB * CC, 256>>>(s1, (float*)d_out, X0);
}

// round 2
// speedup vs baseline: 1.2426x; 1.2426x over previous
#include <cuda_runtime.h>
#include <math.h>

#define BB 8
#define CC 96
#define NN 3136
#define KK 9

// ---------------- scratch (device globals: no allocations allowed) ----------
__device__ float g_y1[BB*CC*NN];
__device__ float g_y1t[BB*NN*CC];
__device__ float g_xn[BB*CC*NN];
__device__ int   g_idx[BB*NN*KK];
__device__ float g_cat[BB*2*CC*NN];
__device__ float g_y2[BB*2*CC*NN];
__device__ float g_t [BB*4*CC*NN];
__device__ float g_s1[BB*CC*NN];
__device__ float g_s2[BB*CC*NN];

// ---------------- generic 1x1-conv GEMM: out[b,o,n] = sum_c W[o,c] in[b,c,n] + bias[o]
#define TN 128
#define TO 32
#define TKC 32
__global__ void gemm_bias_kernel(const float* __restrict__ in, const float* __restrict__ W,
                                 const float* __restrict__ bias, float* __restrict__ out,
                                 int Cin, int Cout)
{
    int b  = blockIdx.z;
    int o0 = blockIdx.y * TO;
    int n0 = blockIdx.x * TN;
    const float* inb = in + (size_t)b * Cin * NN;
    float* outb      = out + (size_t)b * Cout * NN;

    __shared__ float Ws[TKC][TO + 1];
    __shared__ float Is[TKC][TN];

    int tid = threadIdx.x;
    int tx = tid & 31;   // 4 cols each
    int ty = tid >> 5;   // 4 rows each

    float acc[4][4];
    #pragma unroll
    for (int i = 0; i < 4; i++)
        #pragma unroll
        for (int j = 0; j < 4; j++) acc[i][j] = 0.f;

    for (int k0 = 0; k0 < Cin; k0 += TKC) {
        for (int i = tid; i < TO * TKC; i += 256) {
            int o = i >> 5, k = i & 31;
            Ws[k][o] = W[(size_t)(o0 + o) * Cin + k0 + k];
        }
        for (int i = tid; i < TKC * TN; i += 256) {
            int k = i >> 7, n = i & 127;
            int gn = n0 + n;
            Is[k][n] = (gn < NN) ? inb[(size_t)(k0 + k) * NN + gn] : 0.f;
        }
        __syncthreads();
        #pragma unroll 8
        for (int k = 0; k < TKC; k++) {
            float a0 = Ws[k][ty*4+0], a1 = Ws[k][ty*4+1];
            float a2 = Ws[k][ty*4+2], a3 = Ws[k][ty*4+3];
            float4 bv = *(const float4*)&Is[k][tx*4];
            acc[0][0] += a0*bv.x; acc[0][1] += a0*bv.y; acc[0][2] += a0*bv.z; acc[0][3] += a0*bv.w;
            acc[1][0] += a1*bv.x; acc[1][1] += a1*bv.y; acc[1][2] += a1*bv.z; acc[1][3] += a1*bv.w;
            acc[2][0] += a2*bv.x; acc[2][1] += a2*bv.y; acc[2][2] += a2*bv.z; acc[2][3] += a2*bv.w;
            acc[3][0] += a3*bv.x; acc[3][1] += a3*bv.y; acc[3][2] += a3*bv.z; acc[3][3] += a3*bv.w;
        }
        __syncthreads();
    }
    #pragma unroll
    for (int i = 0; i < 4; i++) {
        int o = o0 + ty*4 + i;
        float bb = bias[o];
        #pragma unroll
        for (int j = 0; j < 4; j++) {
            int n = n0 + tx*4 + j;
            if (n < NN) outb[(size_t)o * NN + n] = acc[i][j] + bb;
        }
    }
}

// ---------------- instance norm over N per (b,c) row, with fused epilogues
// EPI: 0=none, 1=gelu(exact), 2=relu, 3=add residual
#define NN4 (NN/4)
template<int EPI>
__global__ void inorm_kernel(const float* __restrict__ in, float* __restrict__ out,
                             const float* __restrict__ res)
{
    int row = blockIdx.x;
    const float4* x4 = (const float4*)(in + (size_t)row * NN);
    float4* y4       = (float4*)(out + (size_t)row * NN);
    const float4* r4 = res ? (const float4*)(res + (size_t)row * NN) : nullptr;

    float s = 0.f, ss = 0.f;
    for (int i = threadIdx.x; i < NN4; i += blockDim.x) {
        float4 v = x4[i];
        s  += v.x + v.y + v.z + v.w;
        ss += v.x*v.x + v.y*v.y + v.z*v.z + v.w*v.w;
    }
    __shared__ float red[2][32];
    #pragma unroll
    for (int o = 16; o; o >>= 1) {
        s  += __shfl_down_sync(0xffffffffu, s,  o);
        ss += __shfl_down_sync(0xffffffffu, ss, o);
    }
    int wid = threadIdx.x >> 5, lid = threadIdx.x & 31;
    if (!lid) { red[0][wid] = s; red[1][wid] = ss; }
    __syncthreads();
    if (wid == 0) {
        s  = (lid < (int)(blockDim.x >> 5)) ? red[0][lid] : 0.f;
        ss = (lid < (int)(blockDim.x >> 5)) ? red[1][lid] : 0.f;
        #pragma unroll
        for (int o = 16; o; o >>= 1) {
            s  += __shfl_down_sync(0xffffffffu, s,  o);
            ss += __shfl_down_sync(0xffffffffu, ss, o);
        }
        if (!lid) { red[0][0] = s; red[1][0] = ss; }
    }
    __syncthreads();
    float mean = red[0][0] * (1.f / NN);
    float var  = red[1][0] * (1.f / NN) - mean * mean;
    float rstd = rsqrtf(var + 1e-5f);
    for (int i = threadIdx.x; i < NN4; i += blockDim.x) {
        float4 v = x4[i];
        float o0 = (v.x - mean) * rstd, o1 = (v.y - mean) * rstd;
        float o2 = (v.z - mean) * rstd, o3 = (v.w - mean) * rstd;
        if (EPI == 1) {
            o0 = 0.5f*o0*(1.f + erff(o0*0.70710678118654752f));
            o1 = 0.5f*o1*(1.f + erff(o1*0.70710678118654752f));
            o2 = 0.5f*o2*(1.f + erff(o2*0.70710678118654752f));
            o3 = 0.5f*o3*(1.f + erff(o3*0.70710678118654752f));
        } else if (EPI == 2) {
            o0 = fmaxf(o0, 0.f); o1 = fmaxf(o1, 0.f);
            o2 = fmaxf(o2, 0.f); o3 = fmaxf(o3, 0.f);
        } else if (EPI == 3) {
            float4 r = r4[i];
            o0 += r.x; o1 += r.y; o2 += r.z; o3 += r.w;
        }
        y4[i] = make_float4(o0, o1, o2, o3);
    }
}

// ---------------- per-pixel L2 normalization over channels (for kNN features)
__global__ void colnorm_kernel(const float* __restrict__ y1, float* __restrict__ xn)
{
    int b = blockIdx.y;
    int n = blockIdx.x * blockDim.x + threadIdx.x;
    if (n >= NN) return;
    const float* p = y1 + (size_t)b * CC * NN + n;
    float v[CC];
    float s = 0.f;
    #pragma unroll
    for (int c = 0; c < CC; c++) { v[c] = p[(size_t)c * NN]; s += v[c] * v[c]; }
    float rn = 1.f / fmaxf(sqrtf(s), 1e-12f);
    float* q = xn + (size_t)b * CC * NN + n;
    #pragma unroll
    for (int c = 0; c < CC; c++) q[(size_t)c * NN] = v[c] * rn;
}

// ---------------- tiled transpose: [b][C][N] -> [b][N][C]
__global__ void transpose_kernel(const float* __restrict__ in, float* __restrict__ out)
{
    __shared__ float tile[32][33];
    int b  = blockIdx.z;
    int n0 = blockIdx.x * 32;
    int c0 = blockIdx.y * 32;
    int x = threadIdx.x, y = threadIdx.y;   // 32 x 8
    #pragma unroll
    for (int i = 0; i < 32; i += 8) {
        int c = c0 + y + i, n = n0 + x;
        tile[y + i][x] = (c < CC && n < NN) ? in[(size_t)b*CC*NN + (size_t)c*NN + n] : 0.f;
    }
    __syncthreads();
    #pragma unroll
    for (int i = 0; i < 32; i += 8) {
        int n = n0 + y + i, c = c0 + x;
        if (n < NN && c < CC)
            out[(size_t)b*NN*CC + (size_t)n*CC + c] = tile[x][y + i];
    }
}

// ---------------- fused distance GEMM + top-K=9 selection (parallel selection)
// score(n,m) = rp[n,m] - 2*dot(xn_n, xn_m)  (sq terms == 1; ordering identical)
#define KTR 64
#define KTC 128
#define SST 132
#define SMEM_KNN ((CC*KTR + CC*KTC + KTR*SST) * 4)

__global__ void __launch_bounds__(256, 2)
knn_kernel(const float* __restrict__ xn, const float* __restrict__ rp,
           int* __restrict__ idx)
{
    extern __shared__ float sm[];
    float* As = sm;                    // [CC][KTR]
    float* Bs = As + CC * KTR;         // [CC][KTC]  (reused as merge buffer at end)
    float* Ss = Bs + CC * KTC;         // [KTR][SST]

    int b  = blockIdx.y;
    int r0 = blockIdx.x * KTR;         // NN = 64*49 exact
    const float* xb = xn + (size_t)b * CC * NN;
    int tid = threadIdx.x;

    // GEMM thread mapping
    int rg = tid >> 4;     // 16 groups * 4 rows = 64 rows
    int cg = tid & 15;     // 16 groups * (4+4) cols

    // selection thread mapping: lane = row for conflict-free Ss reads
    int sr = tid & 63;     // row within tile
    int sq = tid >> 6;     // column quarter (32 cols)

    for (int i = tid; i < CC * KTR; i += 256) {
        int c = i >> 6, r = i & 63;
        As[c * KTR + r] = xb[(size_t)c * NN + r0 + r];
    }

    float best[KK]; int bidx[KK];
    #pragma unroll
    for (int k = 0; k < KK; k++) { best[k] = 3.4e38f; bidx[k] = 0; }

    for (int m0 = 0; m0 < NN; m0 += KTC) {
        // load B tile (prev GEMM reads of Bs are behind last tile's barrier)
        for (int i = tid; i < CC * KTC; i += 256) {
            int c = i >> 7, m = i & 127;
            int gm = m0 + m;
            Bs[c * KTC + m] = (gm < NN) ? xb[(size_t)c * NN + gm] : 0.f;
        }
        __syncthreads();   // Bs ready; prev selection done -> Ss writable

        float acc[4][8];
        #pragma unroll
        for (int i = 0; i < 4; i++)
            #pragma unroll
            for (int j = 0; j < 8; j++) acc[i][j] = 0.f;

        #pragma unroll 4
        for (int c = 0; c < CC; c++) {
            float a0 = As[c*KTR + rg*4 + 0];
            float a1 = As[c*KTR + rg*4 + 1];
            float a2 = As[c*KTR + rg*4 + 2];
            float a3 = As[c*KTR + rg*4 + 3];
            float4 b0 = *(const float4*)&Bs[c*KTC + cg*4];
            float4 b1 = *(const float4*)&Bs[c*KTC + 64 + cg*4];
            acc[0][0] += a0*b0.x; acc[0][1] += a0*b0.y; acc[0][2] += a0*b0.z; acc[0][3] += a0*b0.w;
            acc[0][4] += a0*b1.x; acc[0][5] += a0*b1.y; acc[0][6] += a0*b1.z; acc[0][7] += a0*b1.w;
            acc[1][0] += a1*b0.x; acc[1][1] += a1*b0.y; acc[1][2] += a1*b0.z; acc[1][3] += a1*b0.w;
            acc[1][4] += a1*b1.x; acc[1][5] += a1*b1.y; acc[1][6] += a1*b1.z; acc[1][7] += a1*b1.w;
            acc[2][0] += a2*b0.x; acc[2][1] += a2*b0.y; acc[2][2] += a2*b0.z; acc[2][3] += a2*b0.w;
            acc[2][4] += a2*b1.x; acc[2][5] += a2*b1.y; acc[2][6] += a2*b1.z; acc[2][7] += a2*b1.w;
            acc[3][0] += a3*b0.x; acc[3][1] += a3*b0.y; acc[3][2] += a3*b0.z; acc[3][3] += a3*b0.w;
            acc[3][4] += a3*b1.x; acc[3][5] += a3*b1.y; acc[3][6] += a3*b1.z; acc[3][7] += a3*b1.w;
        }

        // write raw -2-free accumulators as float4 (conflict-free with SST=132)
        #pragma unroll
        for (int i = 0; i < 4; i++) {
            int r = rg*4 + i;
            *(float4*)&Ss[r * SST + cg*4]      = make_float4(acc[i][0], acc[i][1], acc[i][2], acc[i][3]);
            *(float4*)&Ss[r * SST + 64 + cg*4] = make_float4(acc[i][4], acc[i][5], acc[i][6], acc[i][7]);
        }

        // issue rp loads before the barrier (latency overlaps the sync)
        int lim = NN - m0; if (lim > KTC) lim = KTC;
        bool act = (sq * 32 < lim);
        float4 rv[8];
        if (act) {
            const float4* rpr = (const float4*)(rp + (size_t)(r0 + sr) * NN + m0 + sq * 32);
            #pragma unroll
            for (int jj = 0; jj < 8; jj++) rv[jj] = __ldg(rpr + jj);
        }
        __syncthreads();   // Ss ready

        if (act) {
            const float4* sp = (const float4*)&Ss[sr * SST + sq * 32];
            int gbase = m0 + sq * 32;
            #pragma unroll
            for (int jj = 0; jj < 8; jj++) {
                float4 a = sp[jj];
                float4 r = rv[jj];
                float s0 = r.x - 2.f * a.x;
                float s1 = r.y - 2.f * a.y;
                float s2 = r.z - 2.f * a.z;
                float s3 = r.w - 2.f * a.w;
                int g = gbase + jj * 4;
                #pragma unroll
                for (int e = 0; e < 4; e++) {
                    float s = (e == 0) ? s0 : (e == 1) ? s1 : (e == 2) ? s2 : s3;
                    if (s < best[KK-1]) {
                        best[KK-1] = s; bidx[KK-1] = g + e;
                        #pragma unroll
                        for (int k = KK-1; k > 0; k--) {
                            if (best[k] < best[k-1]) {
                                float tv = best[k]; best[k] = best[k-1]; best[k-1] = tv;
                                int   ti = bidx[k]; bidx[k] = bidx[k-1]; bidx[k-1] = ti;
                            }
                        }
                    }
                }
            }
        }
    }

    // merge 4 partial top-9 lists per row (stage into Bs region)
    __syncthreads();
    float* mbv = Bs;                           // [4][64][9]
    int*   mbi = (int*)(Bs + 4 * 64 * KK);     // [4][64][9]
    #pragma unroll
    for (int k = 0; k < KK; k++) {
        mbv[(sq * 64 + sr) * KK + k] = best[k];
        mbi[(sq * 64 + sr) * KK + k] = bidx[k];
    }
    __syncthreads();

    if (tid < 64) {
        int p[4] = {0, 0, 0, 0};
        int* op = idx + ((size_t)b * NN + r0 + tid) * KK;
        #pragma unroll
        for (int k = 0; k < KK; k++) {
            float bv = 3.5e38f; int bi = 0x7fffffff; int bq = 0;
            #pragma unroll
            for (int q = 0; q < 4; q++) {
                if (p[q] < KK) {
                    float v = mbv[(q * 64 + tid) * KK + p[q]];
                    int   i = mbi[(q * 64 + tid) * KK + p[q]];
                    if (v < bv || (v == bv && i < bi)) { bv = v; bi = i; bq = q; }
                }
            }
            op[k] = bi;
            p[bq]++;
        }
    }
}

// ---------------- max-relative gather (from transposed features) + interleaved concat
// cat[b,2c,n] = xf ; cat[b,2c+1,n] = max_k(xf[idx_k]) - xf[n]
__global__ void gather2_kernel(const float* __restrict__ y1t, const int* __restrict__ idx,
                               float* __restrict__ cat)
{
    int b = blockIdx.y;
    int n = blockIdx.x * blockDim.x + threadIdx.x;
    if (n >= NN) return;
    const int* ib = idx + ((size_t)b * NN + n) * KK;
    int j[KK];
    #pragma unroll
    for (int k = 0; k < KK; k++) j[k] = ib[k];

    const float4* base = (const float4*)(y1t + (size_t)b * NN * CC);
    const float4* own  = base + (size_t)n * (CC/4);
    float* cb = cat + (size_t)b * 2 * CC * NN + n;

    #pragma unroll 2
    for (int cc = 0; cc < CC/4; cc++) {
        float4 o = own[cc];
        float4 m = base[(size_t)j[0] * (CC/4) + cc];
        #pragma unroll
        for (int k = 1; k < KK; k++) {
            float4 v = base[(size_t)j[k] * (CC/4) + cc];
            m.x = fmaxf(m.x, v.x); m.y = fmaxf(m.y, v.y);
            m.z = fmaxf(m.z, v.z); m.w = fmaxf(m.w, v.w);
        }
        cb[(size_t)(8*cc + 0) * NN] = o.x;
        cb[(size_t)(8*cc + 1) * NN] = m.x - o.x;
        cb[(size_t)(8*cc + 2) * NN] = o.y;
        cb[(size_t)(8*cc + 3) * NN] = m.y - o.y;
        cb[(size_t)(8*cc + 4) * NN] = o.z;
        cb[(size_t)(8*cc + 5) * NN] = m.z - o.z;
        cb[(size_t)(8*cc + 6) * NN] = o.w;
        cb[(size_t)(8*cc + 7) * NN] = m.w - o.w;
    }
}

// ---------------- host orchestration -----------------------------------------
static void run_grapher(const float* X, const float* rp,
                        const float* fc1w, const float* fc1b,
                        const float* mrw,  const float* mrb,
                        const float* fc2w, const float* fc2b,
                        float* out,
                        float* y1, float* y1t, float* xn, int* idx,
                        float* cat, float* y2, float* t)
{
    dim3 gA((NN + TN - 1) / TN, CC / TO, BB);
    gemm_bias_kernel<<<gA, 256>>>(X, fc1w, fc1b, y1, CC, CC);
    inorm_kernel<0><<<BB * CC, 256>>>(y1, y1, nullptr);
    colnorm_kernel<<<dim3((NN + 255) / 256, BB), 256>>>(y1, xn);
    transpose_kernel<<<dim3((NN + 31) / 32, (CC + 31) / 32, BB), dim3(32, 8)>>>(y1, y1t);
    knn_kernel<<<dim3(NN / KTR, BB), 256, SMEM_KNN>>>(xn, rp, idx);
    gather2_kernel<<<dim3((NN + 255) / 256, BB), 256>>>(y1t, idx, cat);
    dim3 gB((NN + TN - 1) / TN, 2 * CC / TO, BB);
    gemm_bias_kernel<<<gB, 256>>>(cat, mrw, mrb, y2, 2 * CC, 2 * CC);
    inorm_kernel<1><<<BB * 2 * CC, 256>>>(y2, y2, nullptr);
    dim3 gC((NN + TN - 1) / TN, CC / TO, BB);
    gemm_bias_kernel<<<gC, 256>>>(y2, fc2w, fc2b, t, 2 * CC, CC);
    inorm_kernel<3><<<BB * CC, 256>>>(t, out, X);
}

static void run_ffn(const float* X,
                    const float* w1, const float* b1,
                    const float* w2, const float* b2,
                    float* out, float* t, float* y1)
{
    dim3 gA((NN + TN - 1) / TN, 4 * CC / TO, BB);
    gemm_bias_kernel<<<gA, 256>>>(X, w1, b1, t, CC, 4 * CC);
    inorm_kernel<1><<<BB * 4 * CC, 256>>>(t, t, nullptr);
    dim3 gB((NN + TN - 1) / TN, CC / TO, BB);
    gemm_bias_kernel<<<gB, 256>>>(t, w2, b2, y1, 4 * CC, CC);
    inorm_kernel<3><<<BB * CC, 256>>>(y1, out, X);
}

extern "C" void kernel_launch(void* const* d_in, const int* in_sizes, int n_in,
                              void* d_out, int out_size)
{
    const float* X0 = (const float*)d_in[0];
    const float* rp = (const float*)d_in[1];

    float *y1, *y1t, *xn, *cat, *y2, *t, *s1, *s2; int* idx;
    cudaGetSymbolAddress((void**)&y1,  g_y1);
    cudaGetSymbolAddress((void**)&y1t, g_y1t);
    cudaGetSymbolAddress((void**)&xn,  g_xn);
    cudaGetSymbolAddress((void**)&idx, g_idx);
    cudaGetSymbolAddress((void**)&cat, g_cat);
    cudaGetSymbolAddress((void**)&y2,  g_y2);
    cudaGetSymbolAddress((void**)&t,   g_t);
    cudaGetSymbolAddress((void**)&s1,  g_s1);
    cudaGetSymbolAddress((void**)&s2,  g_s2);

    cudaFuncSetAttribute(knn_kernel, cudaFuncAttributeMaxDynamicSharedMemorySize, SMEM_KNN);

    // grapher 1: X0 -> s1
    run_grapher(X0, rp,
                (const float*)d_in[2], (const float*)d_in[3],
                (const float*)d_in[4], (const float*)d_in[5],
                (const float*)d_in[6], (const float*)d_in[7],
                s1, y1, y1t, xn, idx, cat, y2, t);
    // ffn 1: s1 -> s2
    run_ffn(s1,
            (const float*)d_in[14], (const float*)d_in[15],
            (const float*)d_in[16], (const float*)d_in[17],
            s2, t, y1);
    // mid: relu(inorm(s2)) -> s1
    inorm_kernel<2><<<BB * CC, 256>>>(s2, s1, nullptr);
    // grapher 2: s1 -> s2
    run_grapher(s1, rp,
                (const float*)d_in[8],  (const float*)d_in[9],
                (const float*)d_in[10], (const float*)d_in[11],
                (const float*)d_in[12], (const float*)d_in[13],
                s2, y1, y1t, xn, idx, cat, y2, t);
    // ffn 2: s2 -> s1
    run_ffn(s2,
            (const float*)d_in[18], (const float*)d_in[19],
            (const float*)d_in[20], (const float*)d_in[21],
            s1, t, y1);
    // final: out = X0 + inorm(s1)
    inorm_kernel<3><<<BB * CC, 256>>>(s1, (float*)d_out, X0);
}